// round 1
// baseline (speedup 1.0000x reference)
#include <cuda_runtime.h>
#include <math.h>

#define DIMC   768
#define NH     12
#define HD     64
#define BSZ    2
#define TLEN   2048
#define MROWS  (BSZ * TLEN)          // 4096

// ---------------- scratch (device globals; no allocations allowed) ----------
__device__ float g_q[BSZ * NH * TLEN * HD];     // [b,h,t,d]
__device__ float g_k[BSZ * NH * TLEN * HD];
__device__ float g_v[BSZ * NH * TLEN * HD];
__device__ float g_attn[BSZ * TLEN * DIMC];     // [b,t,c]

// ---------------- GEMM: C = A[M,K] @ W[N,K]^T + bias ------------------------
// MODE 0: write into [b,h,t,d] layout (for q/k/v projections)
// MODE 1: plain row-major [M,N]
template <int MODE>
__global__ __launch_bounds__(256)
void gemm_bias_kernel(const float* __restrict__ A, const float* __restrict__ W,
                      const float* __restrict__ bias, float* __restrict__ C,
                      int M, int N, int K) {
    const int BM = 64, BN = 64, BK = 16;
    __shared__ __align__(16) float As[BK][68];
    __shared__ __align__(16) float Bs[BK][68];

    const int tid = threadIdx.x;
    const int tx = tid & 15;
    const int ty = tid >> 4;
    const int row0 = blockIdx.x * BM;
    const int col0 = blockIdx.y * BN;

    const int lrow = tid >> 2;   // 0..63
    const int lc4  = tid & 3;    // 0..3 (which float4 in the 16-wide k strip)

    float acc[4][4] = {};

    for (int k0 = 0; k0 < K; k0 += BK) {
        float4 av = *(const float4*)&A[(size_t)(row0 + lrow) * K + k0 + lc4 * 4];
        float4 bv = *(const float4*)&W[(size_t)(col0 + lrow) * K + k0 + lc4 * 4];
        As[lc4 * 4 + 0][lrow] = av.x;
        As[lc4 * 4 + 1][lrow] = av.y;
        As[lc4 * 4 + 2][lrow] = av.z;
        As[lc4 * 4 + 3][lrow] = av.w;
        Bs[lc4 * 4 + 0][lrow] = bv.x;
        Bs[lc4 * 4 + 1][lrow] = bv.y;
        Bs[lc4 * 4 + 2][lrow] = bv.z;
        Bs[lc4 * 4 + 3][lrow] = bv.w;
        __syncthreads();

        #pragma unroll
        for (int kk = 0; kk < BK; kk++) {
            float4 a = *(const float4*)&As[kk][ty * 4];
            float4 b = *(const float4*)&Bs[kk][tx * 4];
            float af[4] = {a.x, a.y, a.z, a.w};
            float bf[4] = {b.x, b.y, b.z, b.w};
            #pragma unroll
            for (int i = 0; i < 4; i++)
                #pragma unroll
                for (int j = 0; j < 4; j++)
                    acc[i][j] = fmaf(af[i], bf[j], acc[i][j]);
        }
        __syncthreads();
    }

    #pragma unroll
    for (int i = 0; i < 4; i++) {
        int r = row0 + ty * 4 + i;
        #pragma unroll
        for (int j = 0; j < 4; j++) {
            int c = col0 + tx * 4 + j;
            float v = acc[i][j] + bias[c];
            if (MODE == 0) {
                int b = r / TLEN, t = r % TLEN;
                int h = c / HD,   d = c % HD;
                C[(((size_t)b * NH + h) * TLEN + t) * HD + d] = v;
            } else {
                C[(size_t)r * N + c] = v;
            }
        }
    }
}

// ---------------- Attention: online-softmax, 64-query x 64-kv tiles ---------
// grid: (TLEN/64, BSZ*NH), 256 threads, dynamic smem = 4 * 64 * 68 floats
__global__ __launch_bounds__(256)
void attn_kernel(const float* __restrict__ Q, const float* __restrict__ K,
                 const float* __restrict__ V, float* __restrict__ Out) {
    extern __shared__ __align__(16) float sm[];
    float* q_s = sm;                 // [64][68]
    float* k_s = sm + 64 * 68;
    float* v_s = sm + 2 * 64 * 68;
    float* p_s = sm + 3 * 64 * 68;

    const int tid = threadIdx.x;
    const int tx = tid & 15;
    const int ty = tid >> 4;
    const int bh = blockIdx.y;
    const int q0 = blockIdx.x * 64;
    const float scale = 0.125f;    // 1/sqrt(64)

    // load Q tile [64 rows][64 d] -> q_s (row stride 68 floats, 17 float4)
    {
        const float4* Q4 = (const float4*)(Q + ((size_t)bh * TLEN + q0) * HD);
        #pragma unroll
        for (int i = 0; i < 4; i++) {
            int e = tid + i * 256;
            int r = e >> 4, c = e & 15;
            ((float4*)(q_s + r * 68))[c] = Q4[r * 16 + c];
        }
    }

    float m_i[4], l_i[4], o[4][4];
    #pragma unroll
    for (int i = 0; i < 4; i++) {
        m_i[i] = -1e30f;
        l_i[i] = 0.f;
        #pragma unroll
        for (int j = 0; j < 4; j++) o[i][j] = 0.f;
    }
    __syncthreads();

    for (int kt = 0; kt < TLEN; kt += 64) {
        // load K,V tiles
        {
            const float4* K4 = (const float4*)(K + ((size_t)bh * TLEN + kt) * HD);
            const float4* V4 = (const float4*)(V + ((size_t)bh * TLEN + kt) * HD);
            #pragma unroll
            for (int i = 0; i < 4; i++) {
                int e = tid + i * 256;
                int r = e >> 4, c = e & 15;
                ((float4*)(k_s + r * 68))[c] = K4[r * 16 + c];
                ((float4*)(v_s + r * 68))[c] = V4[r * 16 + c];
            }
        }
        __syncthreads();

        // S = Q @ K^T  (4x4 per thread; rows ty*4+i, cols tx*4+j)
        float s[4][4] = {};
        #pragma unroll
        for (int d4 = 0; d4 < 16; d4++) {
            float4 a[4], b[4];
            #pragma unroll
            for (int i = 0; i < 4; i++)
                a[i] = ((const float4*)(q_s + (ty * 4 + i) * 68))[d4];
            #pragma unroll
            for (int j = 0; j < 4; j++)
                b[j] = ((const float4*)(k_s + (tx * 4 + j) * 68))[d4];
            #pragma unroll
            for (int i = 0; i < 4; i++)
                #pragma unroll
                for (int j = 0; j < 4; j++) {
                    s[i][j] = fmaf(a[i].x, b[j].x, s[i][j]);
                    s[i][j] = fmaf(a[i].y, b[j].y, s[i][j]);
                    s[i][j] = fmaf(a[i].z, b[j].z, s[i][j]);
                    s[i][j] = fmaf(a[i].w, b[j].w, s[i][j]);
                }
        }

        // online softmax update per row (16 tx lanes share a row group)
        #pragma unroll
        for (int i = 0; i < 4; i++) {
            #pragma unroll
            for (int j = 0; j < 4; j++) s[i][j] *= scale;
            float rm = fmaxf(fmaxf(s[i][0], s[i][1]), fmaxf(s[i][2], s[i][3]));
            rm = fmaxf(rm, __shfl_xor_sync(0xffffffffu, rm, 1));
            rm = fmaxf(rm, __shfl_xor_sync(0xffffffffu, rm, 2));
            rm = fmaxf(rm, __shfl_xor_sync(0xffffffffu, rm, 4));
            rm = fmaxf(rm, __shfl_xor_sync(0xffffffffu, rm, 8));
            float mn = fmaxf(m_i[i], rm);
            float corr = __expf(m_i[i] - mn);
            float rs = 0.f;
            #pragma unroll
            for (int j = 0; j < 4; j++) {
                s[i][j] = __expf(s[i][j] - mn);
                rs += s[i][j];
            }
            rs += __shfl_xor_sync(0xffffffffu, rs, 1);
            rs += __shfl_xor_sync(0xffffffffu, rs, 2);
            rs += __shfl_xor_sync(0xffffffffu, rs, 4);
            rs += __shfl_xor_sync(0xffffffffu, rs, 8);
            l_i[i] = l_i[i] * corr + rs;
            m_i[i] = mn;
            #pragma unroll
            for (int j = 0; j < 4; j++) {
                o[i][j] *= corr;
                p_s[(ty * 4 + i) * 68 + tx * 4 + j] = s[i][j];
            }
        }
        __syncthreads();

        // O += P @ V  (rows ty*4+i, d columns tx*4..tx*4+3)
        #pragma unroll 8
        for (int kv = 0; kv < 64; kv++) {
            float4 vv = ((const float4*)(v_s + kv * 68))[tx];
            #pragma unroll
            for (int i = 0; i < 4; i++) {
                float p = p_s[(ty * 4 + i) * 68 + kv];
                o[i][0] = fmaf(p, vv.x, o[i][0]);
                o[i][1] = fmaf(p, vv.y, o[i][1]);
                o[i][2] = fmaf(p, vv.z, o[i][2]);
                o[i][3] = fmaf(p, vv.w, o[i][3]);
            }
        }
        __syncthreads();
    }

    // epilogue: write [b,t,c] layout
    const int b = bh / NH, h = bh % NH;
    #pragma unroll
    for (int i = 0; i < 4; i++) {
        int t = q0 + ty * 4 + i;
        float inv = 1.f / l_i[i];
        float4 res = {o[i][0] * inv, o[i][1] * inv, o[i][2] * inv, o[i][3] * inv};
        ((float4*)(Out + ((size_t)b * TLEN + t) * DIMC + h * HD))[tx] = res;
    }
}

// ---------------- launch -----------------------------------------------------
extern "C" void kernel_launch(void* const* d_in, const int* in_sizes, int n_in,
                              void* d_out, int out_size) {
    const float* q_in = (const float*)d_in[0];
    const float* k_in = (const float*)d_in[1];
    const float* v_in = (const float*)d_in[2];
    const float* Wq = (const float*)d_in[3];
    const float* bq = (const float*)d_in[4];
    const float* Wk = (const float*)d_in[5];
    const float* bk = (const float*)d_in[6];
    const float* Wv = (const float*)d_in[7];
    const float* bv = (const float*)d_in[8];
    const float* Wo = (const float*)d_in[9];
    const float* bo = (const float*)d_in[10];
    float* out = (float*)d_out;

    float *pq, *pk, *pv, *pattn;
    cudaGetSymbolAddress((void**)&pq, g_q);
    cudaGetSymbolAddress((void**)&pk, g_k);
    cudaGetSymbolAddress((void**)&pv, g_v);
    cudaGetSymbolAddress((void**)&pattn, g_attn);

    const int attn_smem = 4 * 64 * 68 * (int)sizeof(float);  // 69632 B
    cudaFuncSetAttribute(attn_kernel, cudaFuncAttributeMaxDynamicSharedMemorySize,
                         attn_smem);

    dim3 ggrid(MROWS / 64, DIMC / 64);   // 64 x 12
    gemm_bias_kernel<0><<<ggrid, 256>>>(q_in, Wq, bq, pq, MROWS, DIMC, DIMC);
    gemm_bias_kernel<0><<<ggrid, 256>>>(k_in, Wk, bk, pk, MROWS, DIMC, DIMC);
    gemm_bias_kernel<0><<<ggrid, 256>>>(v_in, Wv, bv, pv, MROWS, DIMC, DIMC);

    dim3 agrid(TLEN / 64, BSZ * NH);     // 32 x 24
    attn_kernel<<<agrid, 256, attn_smem>>>(pq, pk, pv, pattn);

    gemm_bias_kernel<1><<<ggrid, 256>>>(pattn, Wo, bo, out, MROWS, DIMC, DIMC);
}